// round 14
// baseline (speedup 1.0000x reference)
#include <cuda_runtime.h>
#include <cuda_fp16.h>
#include <cstdint>
#include <math.h>

#define BSZ  16384
#define DIN  2048
#define DOUT 2048
#define KTOP 256

#define GEMM_SMEM (2 * 32768)   // 2 stages x (A 16KB + W 16KB), BK=64 fp16

// ---------------- streams/events for fork-join overlap (created ONCE, pre-main;
// no device-memory allocation inside kernel_launch; capture-safe fork-join) ----
static cudaStream_t g_s1;
static cudaEvent_t  g_evM0, g_evJ;
struct _StreamInit {
    _StreamInit() {
        cudaStreamCreateWithFlags(&g_s1, cudaStreamNonBlocking);
        cudaEventCreateWithFlags(&g_evM0, cudaEventDisableTiming);
        cudaEventCreateWithFlags(&g_evJ, cudaEventDisableTiming);
    }
};
static _StreamInit g_si;

// ---------------- scratch (static __device__, no allocation) ----------------
__device__ __half g_Ah[(size_t)BSZ * DIN];   // fragment-permuted fp16 A = owa*x
__device__ __half g_Wh[(size_t)DOUT * DIN];  // fragment-permuted fp16 W
__device__ float  g_out[(size_t)BSZ * DOUT]; // pre-BN activations (fp32)
__device__ float  g_psum[128 * DOUT];        // per-128-row-block column sums
__device__ float  g_psumsq[128 * DOUT];
__device__ float  g_scale[DOUT];
__device__ float  g_shift[DOUT];

// ---------------- fp16 fragment-permuted layouts (m16n8k16) ----------------
__device__ __forceinline__ size_t ah_idx(int row, int d) {
    int bm = row >> 7, rr = row & 127;
    int mi = rr >> 4,  mr = rr & 15;
    int kt = d >> 4,   kk = d & 15;
    int lane = (mr & 7) * 4 + ((kk & 7) >> 1);
    int reg  = (mr >> 3) + 2 * (kk >> 3);
    return (((size_t)(bm * 128 + kt) * 8 + mi) * 32 + lane) * 8 + reg * 2 + (kk & 1);
}

// ---------------- 4-instruction MUFU sigmoid (2 MUFU + FMUL + FADD) --------
// ex2.approx / rcp.approx are deterministic HW functions, rel err ~1e-6.
// Extremes are safe: ex2->inf => rcp->0 (mu=0); ex2->0 => mu=1.
__device__ __forceinline__ float fast_sigmoid(float z) {
    float e;
    asm("ex2.approx.f32 %0, %1;" : "=f"(e) : "f"(-z * 1.4426950408889634f));
    float r;
    float den = 1.0f + e;
    asm("rcp.approx.f32 %0, %1;" : "=f"(r) : "f"(den));
    return r;
}

__device__ __forceinline__ unsigned long long shfl_xor64(unsigned long long v, int m) {
    unsigned lo = (unsigned)v, hi = (unsigned)(v >> 32);
    lo = __shfl_xor_sync(0xFFFFFFFFu, lo, m);
    hi = __shfl_xor_sync(0xFFFFFFFFu, hi, m);
    return ((unsigned long long)hi << 32) | lo;
}

// ---------------- kernel W: convert+permute W to fp16 ----------------------
__global__ void k_wconv(const float* __restrict__ W) {
    int idx = blockIdx.x * 256 + threadIdx.x;     // 262144 total
    int n = idx >> 7, kt = idx & 127;
    const float* src = W + (size_t)n * DIN + kt * 16;
    float4 v0 = ((const float4*)src)[0];
    float4 v1 = ((const float4*)src)[1];
    float4 v2 = ((const float4*)src)[2];
    float4 v3 = ((const float4*)src)[3];
    float vv[16] = {v0.x,v0.y,v0.z,v0.w, v1.x,v1.y,v1.z,v1.w,
                    v2.x,v2.y,v2.z,v2.w, v3.x,v3.y,v3.z,v3.w};
    __half h[16];
#pragma unroll
    for (int k = 0; k < 16; k++) {
        int pos = ((k & 7) >> 1) * 4 + (k >> 3) * 2 + (k & 1);
        h[pos] = __float2half_rn(vv[k]);
    }
    int bn = n >> 7, nr = n & 127, ni = nr >> 3, nn = nr & 7;
    size_t bb = (((size_t)(bn * 128 + kt) * 16 + ni) * 32 + nn * 4) * 4;  // halves
    *reinterpret_cast<uint4*>(&g_Wh[bb])     = *reinterpret_cast<uint4*>(&h[0]);
    *reinterpret_cast<uint4*>(&g_Wh[bb + 8]) = *reinterpret_cast<uint4*>(&h[8]);
}

// ---------------- kernel 1: mu + z-key radix top-256 + rank via sort -------
__global__ __launch_bounds__(256) void k_mu_topk(const float* __restrict__ x,
                                                 const float* __restrict__ center,
                                                 const float* __restrict__ sharp,
                                                 float* __restrict__ mu_out,
                                                 int rowbase) {
    __shared__ float sx[DIN];
    __shared__ int hist[256];
    __shared__ int wsumS[8];
    __shared__ unsigned s_pref;
    __shared__ int s_kk;
    __shared__ int s_g;
    __shared__ unsigned cand[1024];     // boundary-bucket candidates (zkeys)
    __shared__ int candn;
    __shared__ unsigned long long selkey[KTOP];
    __shared__ int scnt;

    int row = blockIdx.x + rowbase, tid = threadIdx.x;
    int lane = tid & 31, wid = tid >> 5;
    const float* xr = x + (size_t)row * DIN;

    float4 x0 = ((const float4*)xr)[tid * 2];
    float4 x1 = ((const float4*)xr)[tid * 2 + 1];
    float4 c0 = ((const float4*)center)[tid * 2];
    float4 c1 = ((const float4*)center)[tid * 2 + 1];
    float4 sh0 = ((const float4*)sharp)[tid * 2];
    float4 sh1 = ((const float4*)sharp)[tid * 2 + 1];
    float xv[8] = {x0.x,x0.y,x0.z,x0.w, x1.x,x1.y,x1.z,x1.w};
    float cc[8] = {c0.x,c0.y,c0.z,c0.w, c1.x,c1.y,c1.z,c1.w};
    float ss[8] = {sh0.x,sh0.y,sh0.z,sh0.w, sh1.x,sh1.y,sh1.z,sh1.w};
    unsigned u[8];
    float muv[8];
#pragma unroll
    for (int j = 0; j < 8; j++) {
        float z = ss[j] * (xv[j] - cc[j]);
        muv[j] = fast_sigmoid(z);
        unsigned zb = __float_as_uint(z);
        u[j] = (zb & 0x80000000u) ? ~zb : (zb | 0x80000000u);   // order-preserving
        sx[tid * 8 + j] = xv[j];
    }
    float* mo = mu_out + (size_t)row * DIN;
    ((float4*)mo)[tid * 2]     = make_float4(muv[0], muv[1], muv[2], muv[3]);
    ((float4*)mo)[tid * 2 + 1] = make_float4(muv[4], muv[5], muv[6], muv[7]);
    if (tid == 0) { scnt = 0; candn = 0; }
    __syncthreads();

    unsigned prefix = 0;
    int kk = KTOP;
    int S = 0;
    bool tie = false;

    // ---- pass 0 over registers (shift 24); z-key digits cluster -> few ATOMS
    hist[tid] = 0;
    __syncthreads();
#pragma unroll
    for (int j = 0; j < 8; j++) {
        int dg = (int)(u[j] >> 24);
        unsigned mk = __match_any_sync(0xFFFFFFFFu, dg);
        if ((int)(__ffs(mk) - 1) == lane)
            atomicAdd(&hist[dg], __popc(mk));
    }
    __syncthreads();
    {
        int h = hist[tid];
        int s = h;
#pragma unroll
        for (int off = 1; off < 32; off <<= 1) {
            int v = __shfl_down_sync(0xFFFFFFFFu, s, off);
            if (lane + off < 32) s += v;
        }
        if (lane == 0) wsumS[wid] = s;
        __syncthreads();
        int wsuf = 0;
        for (int w = wid + 1; w < 8; w++) wsuf += wsumS[w];
        int acc_incl = s + wsuf;
        int acc_excl = acc_incl - h;
        if (acc_excl < kk && kk <= acc_incl) {
            s_pref = (unsigned)tid << 24;
            s_kk = kk - acc_excl;
            s_g = h;
        }
        __syncthreads();
        prefix = s_pref;
        kk = s_kk;
    }

    if (kk == s_g) {
        S = 24;                                        // whole bucket taken
    } else {
        // ---- compact boundary-bucket candidates (~400, bound << 1024)
        unsigned b1 = prefix >> 24;
#pragma unroll
        for (int j = 0; j < 8; j++) {
            if ((u[j] >> 24) == b1) {
                int p = atomicAdd(&candn, 1);
                if (p < 1024) cand[p] = u[j];
            }
        }
        __syncthreads();
        int NC = candn < 1024 ? candn : 1024;
        int iters = (NC + 255) >> 8;                   // uniform across block

        bool done = false;
#pragma unroll 1
        for (int p = 1; p < 4 && !done; p++) {
            int shift = 24 - p * 8;
            hist[tid] = 0;
            __syncthreads();
#pragma unroll 1
            for (int it = 0; it < iters; it++) {
                int c = tid + it * 256;                // c <= 1023 always
                unsigned uv = cand[c];
                bool ok = (c < NC) && (((uv ^ prefix) >> shift) < 256u);
                int dg = ok ? (int)((uv >> shift) & 255) : 256;
                unsigned mk = __match_any_sync(0xFFFFFFFFu, dg);
                if (ok && ((int)(__ffs(mk) - 1) == lane))
                    atomicAdd(&hist[dg], __popc(mk));
            }
            __syncthreads();
            int h = hist[tid];
            int s = h;
#pragma unroll
            for (int off = 1; off < 32; off <<= 1) {
                int v = __shfl_down_sync(0xFFFFFFFFu, s, off);
                if (lane + off < 32) s += v;
            }
            if (lane == 0) wsumS[wid] = s;
            __syncthreads();
            int wsuf = 0;
            for (int w = wid + 1; w < 8; w++) wsuf += wsumS[w];
            int acc_incl = s + wsuf;
            int acc_excl = acc_incl - h;
            if (acc_excl < kk && kk <= acc_incl) {
                s_pref = prefix | ((unsigned)tid << shift);
                s_kk = kk - acc_excl;
                s_g = h;
            }
            __syncthreads();
            prefix = s_pref;
            kk = s_kk;
            if (kk == s_g) { S = shift; done = true; }
        }
        if (!done) { S = 0; tie = true; }              // exact zkey ties at boundary
    }

    // tie fallback: first kk duplicates of value==prefix, by ascending index
    int trun = 0;
    if (tie) {
        int myt = 0;
#pragma unroll
        for (int j = 0; j < 8; j++) myt += (u[j] == prefix);
        int inc = myt;
#pragma unroll
        for (int off = 1; off < 32; off <<= 1) {
            int v = __shfl_up_sync(0xFFFFFFFFu, inc, off);
            if (lane >= off) inc += v;
        }
        if (lane == 31) wsumS[wid] = inc;
        __syncthreads();
        int wbase = 0;
        for (int w = 0; w < wid; w++) wbase += wsumS[w];
        trun = wbase + inc - myt;
    }

    // compact the selected 256 (64-bit keys: zkey | index tiebreak)
    unsigned Pp = prefix >> S;
#pragma unroll
    for (int j = 0; j < 8; j++) {
        unsigned uv = u[j] >> S;
        bool sel = false;
        if (uv > Pp) sel = true;
        else if (uv == Pp) {
            if (!tie) sel = true;
            else { sel = (trun < kk); trun++; }
        }
        if (sel) {
            int d = tid * 8 + j;
            int pp = atomicAdd(&scnt, 1);
            if (pp < KTOP)
                selkey[pp] = ((unsigned long long)u[j] << 11) | (unsigned)(DIN - 1 - d);
        }
    }
    __syncthreads();

    // in-warp bitonic sort (descending), keys unique
    unsigned long long key = selkey[wid * 32 + lane];
#pragma unroll
    for (int k = 2; k <= 32; k <<= 1)
#pragma unroll
        for (int j = k >> 1; j > 0; j >>= 1) {
            unsigned long long other = shfl_xor64(key, j);
            bool keepMax = (((lane & j) == 0) == ((lane & k) == 0));
            bool gt = key > other;
            key = (gt == keepMax) ? key : other;
        }
    selkey[wid * 32 + lane] = key;
    __syncthreads();

    int rank = lane;
#pragma unroll
    for (int r = 0; r < 8; r++) {
        if (r == wid) continue;
        const unsigned long long* run = &selkey[r * 32];
        int c = 0;
        if (run[15]    > key) c = 16;
        if (run[c + 7] > key) c += 8;
        if (run[c + 3] > key) c += 4;
        if (run[c + 1] > key) c += 2;
        if (run[c]     > key) c += 1;
        if (c == 31 && run[31] > key) c = 32;
        rank += c;
    }

    int d = 2047 - (int)(key & 2047);
    unsigned zk = (unsigned)(key >> 11);
    unsigned zb = (zk & 0x80000000u) ? (zk ^ 0x80000000u) : ~zk;  // un-flip
    float z = __uint_as_float(zb);
    float m = fast_sigmoid(z);                          // bitwise == mu used above
    float w = (1.0f - 0.9f * (float)rank * (1.0f / 255.0f)) * (1.0f / 140.8f);
    float a = w * m * sx[d];
    g_Ah[ah_idx(row, d)] = __float2half_rn(a);
}

// ---------------- kernel 2: fp16 GEMM, 2-stage, 3 CTAs/SM, fused colsum ----
__device__ __forceinline__ void fill2(const __half* __restrict__ Ab,
                                      const __half* __restrict__ Wb,
                                      unsigned sdst, int f, int tid) {
    const char* as = (const char*)(Ab + (size_t)f * 8192);
    const char* ws = (const char*)(Wb + (size_t)f * 8192);
#pragma unroll
    for (int i = 0; i < 8; i++) {
        int ch = tid + i * 128;                      // 0..1023
        asm volatile("cp.async.cg.shared.global [%0], [%1], 16;\n"
                     :: "r"(sdst + ch * 16), "l"(as + ch * 16));
        asm volatile("cp.async.cg.shared.global [%0], [%1], 16;\n"
                     :: "r"(sdst + 16384 + ch * 16), "l"(ws + ch * 16));
    }
}

__global__ __launch_bounds__(128, 3) void k_gemm(const float* __restrict__ bias, int bmbase) {
    extern __shared__ char smem[];
    int tid = threadIdx.x, lane = tid & 31, wid = tid >> 5;
    int wm = wid >> 1, wn = wid & 1;                 // 2x2 warp grid, 64x64 tiles
    int bm = blockIdx.y + bmbase, bn = blockIdx.x;
    const __half* Ab = g_Ah + (size_t)bm * 128 * 2048;
    const __half* Wb = g_Wh + (size_t)bn * 128 * 2048;
    unsigned s0 = (unsigned)__cvta_generic_to_shared(smem);

    float c[4][8][4];
#pragma unroll
    for (int i = 0; i < 4; i++)
#pragma unroll
        for (int j = 0; j < 8; j++)
#pragma unroll
            for (int r = 0; r < 4; r++) c[i][j][r] = 0.f;

    fill2(Ab, Wb, s0, 0, tid);
    asm volatile("cp.async.commit_group;\n");
    fill2(Ab, Wb, s0 + 32768, 1, tid);
    asm volatile("cp.async.commit_group;\n");

#pragma unroll 1
    for (int f = 0; f < 32; f++) {
        asm volatile("cp.async.wait_group 1;\n" ::: "memory");  // stage f landed
        __syncthreads();
        const char* a_sb = smem + (f & 1) * 32768;
        const char* w_sb = a_sb + 16384;
#pragma unroll
        for (int kt4 = 0; kt4 < 4; kt4++) {
            uint4 af[4];
#pragma unroll
            for (int i = 0; i < 4; i++) {
                int mi = wm * 4 + i;
                af[i] = *reinterpret_cast<const uint4*>(a_sb + kt4 * 4096 + mi * 512 + lane * 16);
            }
#pragma unroll
            for (int jp = 0; jp < 4; jp++) {
                int ni = wn * 8 + jp * 2;
                uint2 b0 = *reinterpret_cast<const uint2*>(w_sb + kt4 * 4096 + ni * 256 + lane * 8);
                uint2 b1 = *reinterpret_cast<const uint2*>(w_sb + kt4 * 4096 + (ni + 1) * 256 + lane * 8);
#pragma unroll
                for (int i = 0; i < 4; i++) {
                    asm volatile(
                        "mma.sync.aligned.m16n8k16.row.col.f32.f16.f16.f32 "
                        "{%0,%1,%2,%3},{%4,%5,%6,%7},{%8,%9},{%0,%1,%2,%3};\n"
                        : "+f"(c[i][jp*2][0]), "+f"(c[i][jp*2][1]), "+f"(c[i][jp*2][2]), "+f"(c[i][jp*2][3])
                        : "r"(af[i].x), "r"(af[i].y), "r"(af[i].z), "r"(af[i].w),
                          "r"(b0.x), "r"(b0.y));
                    asm volatile(
                        "mma.sync.aligned.m16n8k16.row.col.f32.f16.f16.f32 "
                        "{%0,%1,%2,%3},{%4,%5,%6,%7},{%8,%9},{%0,%1,%2,%3};\n"
                        : "+f"(c[i][jp*2+1][0]), "+f"(c[i][jp*2+1][1]), "+f"(c[i][jp*2+1][2]), "+f"(c[i][jp*2+1][3])
                        : "r"(af[i].x), "r"(af[i].y), "r"(af[i].z), "r"(af[i].w),
                          "r"(b1.x), "r"(b1.y));
                }
            }
        }
        __syncthreads();                              // all readers of buf f&1 done
        if (f + 2 < 32) fill2(Ab, Wb, s0 + (f & 1) * 32768, f + 2, tid);
        asm volatile("cp.async.commit_group;\n");
    }

    // epilogue: bias + relu + fp32 store + fused column sum/sumsq
    float* sWsum = (float*)smem;          // [2][128] indexed by wm
    float* sWsq  = (float*)smem + 256;
    int g = lane >> 2, c2 = (lane & 3) * 2;
#pragma unroll
    for (int j = 0; j < 8; j++) {
        int col = bn * 128 + wn * 64 + j * 8 + c2;
        float b0 = bias[col], b1 = bias[col + 1];
        float sA = 0.f, sB = 0.f, qA = 0.f, qB = 0.f;
#pragma unroll
        for (int i = 0; i < 4; i++) {
            int row0 = bm * 128 + wm * 64 + i * 16 + g;
            float2 v0 = make_float2(fmaxf(c[i][j][0] + b0, 0.f), fmaxf(c[i][j][1] + b1, 0.f));
            float2 v1 = make_float2(fmaxf(c[i][j][2] + b0, 0.f), fmaxf(c[i][j][3] + b1, 0.f));
            *reinterpret_cast<float2*>(&g_out[(size_t)row0 * 2048 + col]) = v0;
            *reinterpret_cast<float2*>(&g_out[(size_t)(row0 + 8) * 2048 + col]) = v1;
            sA += v0.x + v1.x; qA += v0.x * v0.x + v1.x * v1.x;
            sB += v0.y + v1.y; qB += v0.y * v0.y + v1.y * v1.y;
        }
#pragma unroll
        for (int m = 4; m <= 16; m <<= 1) {
            sA += __shfl_xor_sync(0xFFFFFFFFu, sA, m);
            sB += __shfl_xor_sync(0xFFFFFFFFu, sB, m);
            qA += __shfl_xor_sync(0xFFFFFFFFu, qA, m);
            qB += __shfl_xor_sync(0xFFFFFFFFu, qB, m);
        }
        if (lane < 4) {
            int cl = wn * 64 + j * 8 + lane * 2;
            sWsum[wm * 128 + cl]     = sA;
            sWsum[wm * 128 + cl + 1] = sB;
            sWsq[wm * 128 + cl]      = qA;
            sWsq[wm * 128 + cl + 1]  = qB;
        }
    }
    __syncthreads();
    size_t po = (size_t)bm * 2048 + bn * 128 + tid;
    g_psum[po]   = sWsum[tid] + sWsum[128 + tid];
    g_psumsq[po] = sWsq[tid]  + sWsq[128 + tid];
}

// ---------------- kernel 4: finalize mean/var (parallel) -------------------
__global__ void k_final(const float* __restrict__ gamma, const float* __restrict__ beta) {
    int col = blockIdx.x * 32 + (threadIdx.x >> 3);   // 64 blocks x 32 cols
    int part = threadIdx.x & 7;
    float s = 0.f, ss = 0.f;
#pragma unroll
    for (int ch = part; ch < 128; ch += 8) {
        s  += g_psum[(size_t)ch * 2048 + col];
        ss += g_psumsq[(size_t)ch * 2048 + col];
    }
#pragma unroll
    for (int off = 4; off > 0; off >>= 1) {
        s  += __shfl_down_sync(0xFFFFFFFFu, s, off, 8);
        ss += __shfl_down_sync(0xFFFFFFFFu, ss, off, 8);
    }
    if (part == 0) {
        float mean = s * (1.0f / 16384.0f);
        float var = ss * (1.0f / 16384.0f) - mean * mean;
        float inv = rsqrtf(var + 1e-5f);
        float sc = inv * gamma[col];
        g_scale[col] = sc;
        g_shift[col] = beta[col] - mean * sc;
    }
}

// ---------------- kernel 5: apply BN affine --------------------------------
__global__ void k_apply(float* __restrict__ y) {
    size_t idx = (size_t)blockIdx.x * blockDim.x + threadIdx.x;
    float4 v = reinterpret_cast<const float4*>(g_out)[idx];
    int col = ((int)idx * 4) & 2047;
    float4 r;
    r.x = v.x * g_scale[col]     + g_shift[col];
    r.y = v.y * g_scale[col + 1] + g_shift[col + 1];
    r.z = v.z * g_scale[col + 2] + g_shift[col + 2];
    r.w = v.w * g_scale[col + 3] + g_shift[col + 3];
    reinterpret_cast<float4*>(y)[idx] = r;
}

// ---------------- launch: fork-join overlap of mu half-1 with gemm half-0 ---
extern "C" void kernel_launch(void* const* d_in, const int* in_sizes, int n_in,
                              void* d_out, int out_size) {
    (void)in_sizes; (void)n_in; (void)out_size;
    const float* x      = (const float*)d_in[0];
    const float* W      = (const float*)d_in[1];
    const float* bias   = (const float*)d_in[2];
    const float* center = (const float*)d_in[3];
    const float* sharp  = (const float*)d_in[4];
    const float* gamma  = (const float*)d_in[5];
    const float* beta   = (const float*)d_in[6];
    float* y      = (float*)d_out;                       // [B, DOUT]
    float* mu_out = (float*)d_out + (size_t)BSZ * DOUT;  // [B, DIN]

    cudaFuncSetAttribute(k_gemm, cudaFuncAttributeMaxDynamicSharedMemorySize, GEMM_SMEM);

    // s0: wconv -> mu half0
    k_wconv<<<1024, 256>>>(W);
    k_mu_topk<<<BSZ / 2, 256>>>(x, center, sharp, mu_out, 0);
    cudaEventRecord(g_evM0, 0);

    // s1 (forked after mu0): mu half1 runs concurrently with gemm half0 on s0
    cudaStreamWaitEvent(g_s1, g_evM0, 0);
    k_mu_topk<<<BSZ / 2, 256, 0, g_s1>>>(x, center, sharp, mu_out, BSZ / 2);
    k_gemm<<<dim3(DOUT / 128, 64), 128, GEMM_SMEM>>>(bias, 0);          // bm 0..63
    k_gemm<<<dim3(DOUT / 128, 64), 128, GEMM_SMEM, g_s1>>>(bias, 64);   // bm 64..127
    cudaEventRecord(g_evJ, g_s1);

    // join: BN finalize + apply need both gemm halves
    cudaStreamWaitEvent(0, g_evJ, 0);
    k_final<<<64, 256>>>(gamma, beta);
    k_apply<<<32768, 256>>>(y);
}

// round 16
// speedup vs baseline: 1.0282x; 1.0282x over previous
#include <cuda_runtime.h>
#include <cuda_fp16.h>
#include <cstdint>
#include <math.h>

#define BSZ  16384
#define DIN  2048
#define DOUT 2048
#define KTOP 256

#define GEMM_SMEM (2 * 32768)   // 2 stages x (A 16KB + W 16KB), BK=64 fp16

// ---------------- streams/events for fork-join overlap (created ONCE, pre-main;
// no device-memory allocation inside kernel_launch; capture-safe fork-join:
// the side stream's FIRST op is a wait on an event recorded in the origin
// stream — required for stream-capture legality) -----------------------------
static cudaStream_t g_s1;
static cudaEvent_t  g_evM0, g_evJ;
struct _StreamInit {
    _StreamInit() {
        cudaStreamCreateWithFlags(&g_s1, cudaStreamNonBlocking);
        cudaEventCreateWithFlags(&g_evM0, cudaEventDisableTiming);
        cudaEventCreateWithFlags(&g_evJ, cudaEventDisableTiming);
    }
};
static _StreamInit g_si;

// ---------------- scratch (static __device__, no allocation) ----------------
__device__ __half g_Ah[(size_t)BSZ * DIN];   // fragment-permuted fp16 A = owa*x
__device__ __half g_Wh[(size_t)DOUT * DIN];  // fragment-permuted fp16 W
__device__ float  g_out[(size_t)BSZ * DOUT]; // pre-BN activations (fp32)
__device__ float  g_psum[128 * DOUT];        // per-128-row-block column sums
__device__ float  g_psumsq[128 * DOUT];
__device__ float  g_scale[DOUT];
__device__ float  g_shift[DOUT];

// ---------------- fp16 fragment-permuted layouts (m16n8k16) ----------------
__device__ __forceinline__ size_t ah_idx(int row, int d) {
    int bm = row >> 7, rr = row & 127;
    int mi = rr >> 4,  mr = rr & 15;
    int kt = d >> 4,   kk = d & 15;
    int lane = (mr & 7) * 4 + ((kk & 7) >> 1);
    int reg  = (mr >> 3) + 2 * (kk >> 3);
    return (((size_t)(bm * 128 + kt) * 8 + mi) * 32 + lane) * 8 + reg * 2 + (kk & 1);
}

// ---------------- MUFU-free sigmoid (FFMA/ALU only) ------------------------
__device__ __forceinline__ float fast_sigmoid(float z) {
    float t = fminf(fmaxf(-z * 1.4426950408889634f, -126.f), 126.f);
    float tr = t + 12582912.f;                        // round-to-nearest int
    int   n  = __float_as_int(tr) - 0x4B400000;
    float f  = t - (tr - 12582912.f);                 // f in [-0.5, 0.5]
    float p  = 1.3333558e-3f;                         // 2^f poly, deg 5
    p = fmaf(p, f, 9.6181291e-3f);
    p = fmaf(p, f, 5.5504109e-2f);
    p = fmaf(p, f, 2.4022651e-1f);
    p = fmaf(p, f, 6.9314718e-1f);
    p = fmaf(p, f, 1.0f);
    float e = p * __int_as_float((n + 127) << 23);    // exp(-z)
    float den = 1.f + e;
    float r = __int_as_float(0x7EF311C3 - __float_as_int(den));
    r = r * (2.f - den * r);
    r = r * (2.f - den * r);
    return r;
}

__device__ __forceinline__ unsigned long long shfl_xor64(unsigned long long v, int m) {
    unsigned lo = (unsigned)v, hi = (unsigned)(v >> 32);
    lo = __shfl_xor_sync(0xFFFFFFFFu, lo, m);
    hi = __shfl_xor_sync(0xFFFFFFFFu, hi, m);
    return ((unsigned long long)hi << 32) | lo;
}

// ---------------- kernel W: convert+permute W to fp16 ----------------------
__global__ void k_wconv(const float* __restrict__ W) {
    int idx = blockIdx.x * 256 + threadIdx.x;     // 262144 total
    int n = idx >> 7, kt = idx & 127;
    const float* src = W + (size_t)n * DIN + kt * 16;
    float4 v0 = ((const float4*)src)[0];
    float4 v1 = ((const float4*)src)[1];
    float4 v2 = ((const float4*)src)[2];
    float4 v3 = ((const float4*)src)[3];
    float vv[16] = {v0.x,v0.y,v0.z,v0.w, v1.x,v1.y,v1.z,v1.w,
                    v2.x,v2.y,v2.z,v2.w, v3.x,v3.y,v3.z,v3.w};
    __half h[16];
#pragma unroll
    for (int k = 0; k < 16; k++) {
        int pos = ((k & 7) >> 1) * 4 + (k >> 3) * 2 + (k & 1);
        h[pos] = __float2half_rn(vv[k]);
    }
    int bn = n >> 7, nr = n & 127, ni = nr >> 3, nn = nr & 7;
    size_t bb = (((size_t)(bn * 128 + kt) * 16 + ni) * 32 + nn * 4) * 4;  // halves
    *reinterpret_cast<uint4*>(&g_Wh[bb])     = *reinterpret_cast<uint4*>(&h[0]);
    *reinterpret_cast<uint4*>(&g_Wh[bb + 8]) = *reinterpret_cast<uint4*>(&h[8]);
}

// ---------------- kernel 1: mu + z-key radix top-256 + rank via sort -------
__global__ __launch_bounds__(256) void k_mu_topk(const float* __restrict__ x,
                                                 const float* __restrict__ center,
                                                 const float* __restrict__ sharp,
                                                 float* __restrict__ mu_out,
                                                 int rowbase) {
    __shared__ float sx[DIN];
    __shared__ int hist[256];
    __shared__ int wsumS[8];
    __shared__ unsigned s_pref;
    __shared__ int s_kk;
    __shared__ int s_g;
    __shared__ unsigned cand[1024];     // boundary-bucket candidates (zkeys)
    __shared__ int candn;
    __shared__ unsigned long long selkey[KTOP];
    __shared__ int scnt;

    int row = blockIdx.x + rowbase, tid = threadIdx.x;
    int lane = tid & 31, wid = tid >> 5;
    const float* xr = x + (size_t)row * DIN;

    float4 x0 = ((const float4*)xr)[tid * 2];
    float4 x1 = ((const float4*)xr)[tid * 2 + 1];
    float4 c0 = ((const float4*)center)[tid * 2];
    float4 c1 = ((const float4*)center)[tid * 2 + 1];
    float4 sh0 = ((const float4*)sharp)[tid * 2];
    float4 sh1 = ((const float4*)sharp)[tid * 2 + 1];
    float xv[8] = {x0.x,x0.y,x0.z,x0.w, x1.x,x1.y,x1.z,x1.w};
    float cc[8] = {c0.x,c0.y,c0.z,c0.w, c1.x,c1.y,c1.z,c1.w};
    float ss[8] = {sh0.x,sh0.y,sh0.z,sh0.w, sh1.x,sh1.y,sh1.z,sh1.w};
    unsigned u[8];
    float muv[8];
#pragma unroll
    for (int j = 0; j < 8; j++) {
        float z = ss[j] * (xv[j] - cc[j]);
        muv[j] = fast_sigmoid(z);
        unsigned zb = __float_as_uint(z);
        u[j] = (zb & 0x80000000u) ? ~zb : (zb | 0x80000000u);   // order-preserving
        sx[tid * 8 + j] = xv[j];
    }
    float* mo = mu_out + (size_t)row * DIN;
    ((float4*)mo)[tid * 2]     = make_float4(muv[0], muv[1], muv[2], muv[3]);
    ((float4*)mo)[tid * 2 + 1] = make_float4(muv[4], muv[5], muv[6], muv[7]);
    if (tid == 0) { scnt = 0; candn = 0; }
    __syncthreads();

    unsigned prefix = 0;
    int kk = KTOP;
    int S = 0;
    bool tie = false;

    // ---- pass 0 over registers (shift 24); z-key digits cluster -> few ATOMS
    hist[tid] = 0;
    __syncthreads();
#pragma unroll
    for (int j = 0; j < 8; j++) {
        int dg = (int)(u[j] >> 24);
        unsigned mk = __match_any_sync(0xFFFFFFFFu, dg);
        if ((int)(__ffs(mk) - 1) == lane)
            atomicAdd(&hist[dg], __popc(mk));
    }
    __syncthreads();
    {
        int h = hist[tid];
        int s = h;
#pragma unroll
        for (int off = 1; off < 32; off <<= 1) {
            int v = __shfl_down_sync(0xFFFFFFFFu, s, off);
            if (lane + off < 32) s += v;
        }
        if (lane == 0) wsumS[wid] = s;
        __syncthreads();
        int wsuf = 0;
        for (int w = wid + 1; w < 8; w++) wsuf += wsumS[w];
        int acc_incl = s + wsuf;
        int acc_excl = acc_incl - h;
        if (acc_excl < kk && kk <= acc_incl) {
            s_pref = (unsigned)tid << 24;
            s_kk = kk - acc_excl;
            s_g = h;
        }
        __syncthreads();
        prefix = s_pref;
        kk = s_kk;
    }

    if (kk == s_g) {
        S = 24;                                        // whole bucket taken
    } else {
        // ---- compact boundary-bucket candidates (~400, bound << 1024)
        unsigned b1 = prefix >> 24;
#pragma unroll
        for (int j = 0; j < 8; j++) {
            if ((u[j] >> 24) == b1) {
                int p = atomicAdd(&candn, 1);
                if (p < 1024) cand[p] = u[j];
            }
        }
        __syncthreads();
        int NC = candn < 1024 ? candn : 1024;
        int iters = (NC + 255) >> 8;                   // uniform across block

        bool done = false;
#pragma unroll 1
        for (int p = 1; p < 4 && !done; p++) {
            int shift = 24 - p * 8;
            hist[tid] = 0;
            __syncthreads();
#pragma unroll 1
            for (int it = 0; it < iters; it++) {
                int c = tid + it * 256;                // c <= 1023 always
                unsigned uv = cand[c];
                bool ok = (c < NC) && (((uv ^ prefix) >> shift) < 256u);
                int dg = ok ? (int)((uv >> shift) & 255) : 256;
                unsigned mk = __match_any_sync(0xFFFFFFFFu, dg);
                if (ok && ((int)(__ffs(mk) - 1) == lane))
                    atomicAdd(&hist[dg], __popc(mk));
            }
            __syncthreads();
            int h = hist[tid];
            int s = h;
#pragma unroll
            for (int off = 1; off < 32; off <<= 1) {
                int v = __shfl_down_sync(0xFFFFFFFFu, s, off);
                if (lane + off < 32) s += v;
            }
            if (lane == 0) wsumS[wid] = s;
            __syncthreads();
            int wsuf = 0;
            for (int w = wid + 1; w < 8; w++) wsuf += wsumS[w];
            int acc_incl = s + wsuf;
            int acc_excl = acc_incl - h;
            if (acc_excl < kk && kk <= acc_incl) {
                s_pref = prefix | ((unsigned)tid << shift);
                s_kk = kk - acc_excl;
                s_g = h;
            }
            __syncthreads();
            prefix = s_pref;
            kk = s_kk;
            if (kk == s_g) { S = shift; done = true; }
        }
        if (!done) { S = 0; tie = true; }              // exact zkey ties at boundary
    }

    // tie fallback: first kk duplicates of value==prefix, by ascending index
    int trun = 0;
    if (tie) {
        int myt = 0;
#pragma unroll
        for (int j = 0; j < 8; j++) myt += (u[j] == prefix);
        int inc = myt;
#pragma unroll
        for (int off = 1; off < 32; off <<= 1) {
            int v = __shfl_up_sync(0xFFFFFFFFu, inc, off);
            if (lane >= off) inc += v;
        }
        if (lane == 31) wsumS[wid] = inc;
        __syncthreads();
        int wbase = 0;
        for (int w = 0; w < wid; w++) wbase += wsumS[w];
        trun = wbase + inc - myt;
    }

    // compact the selected 256 (64-bit keys: zkey | index tiebreak)
    unsigned Pp = prefix >> S;
#pragma unroll
    for (int j = 0; j < 8; j++) {
        unsigned uv = u[j] >> S;
        bool sel = false;
        if (uv > Pp) sel = true;
        else if (uv == Pp) {
            if (!tie) sel = true;
            else { sel = (trun < kk); trun++; }
        }
        if (sel) {
            int d = tid * 8 + j;
            int pp = atomicAdd(&scnt, 1);
            if (pp < KTOP)
                selkey[pp] = ((unsigned long long)u[j] << 11) | (unsigned)(DIN - 1 - d);
        }
    }
    __syncthreads();

    // in-warp bitonic sort (descending), keys unique
    unsigned long long key = selkey[wid * 32 + lane];
#pragma unroll
    for (int k = 2; k <= 32; k <<= 1)
#pragma unroll
        for (int j = k >> 1; j > 0; j >>= 1) {
            unsigned long long other = shfl_xor64(key, j);
            bool keepMax = (((lane & j) == 0) == ((lane & k) == 0));
            bool gt = key > other;
            key = (gt == keepMax) ? key : other;
        }
    selkey[wid * 32 + lane] = key;
    __syncthreads();

    int rank = lane;
#pragma unroll
    for (int r = 0; r < 8; r++) {
        if (r == wid) continue;
        const unsigned long long* run = &selkey[r * 32];
        int c = 0;
        if (run[15]    > key) c = 16;
        if (run[c + 7] > key) c += 8;
        if (run[c + 3] > key) c += 4;
        if (run[c + 1] > key) c += 2;
        if (run[c]     > key) c += 1;
        if (c == 31 && run[31] > key) c = 32;
        rank += c;
    }

    int d = 2047 - (int)(key & 2047);
    unsigned zk = (unsigned)(key >> 11);
    unsigned zb = (zk & 0x80000000u) ? (zk ^ 0x80000000u) : ~zk;  // un-flip
    float z = __uint_as_float(zb);
    float m = fast_sigmoid(z);                          // bitwise == mu used above
    float w = (1.0f - 0.9f * (float)rank * (1.0f / 255.0f)) * (1.0f / 140.8f);
    float a = w * m * sx[d];
    g_Ah[ah_idx(row, d)] = __float2half_rn(a);
}

// ---------------- kernel 2: fp16 GEMM, 2-stage, 3 CTAs/SM, fused colsum ----
__device__ __forceinline__ void fill2(const __half* __restrict__ Ab,
                                      const __half* __restrict__ Wb,
                                      unsigned sdst, int f, int tid) {
    const char* as = (const char*)(Ab + (size_t)f * 8192);
    const char* ws = (const char*)(Wb + (size_t)f * 8192);
#pragma unroll
    for (int i = 0; i < 8; i++) {
        int ch = tid + i * 128;                      // 0..1023
        asm volatile("cp.async.cg.shared.global [%0], [%1], 16;\n"
                     :: "r"(sdst + ch * 16), "l"(as + ch * 16));
        asm volatile("cp.async.cg.shared.global [%0], [%1], 16;\n"
                     :: "r"(sdst + 16384 + ch * 16), "l"(ws + ch * 16));
    }
}

__global__ __launch_bounds__(128, 3) void k_gemm(const float* __restrict__ bias, int bmbase) {
    extern __shared__ char smem[];
    int tid = threadIdx.x, lane = tid & 31, wid = tid >> 5;
    int wm = wid >> 1, wn = wid & 1;                 // 2x2 warp grid, 64x64 tiles
    int bm = blockIdx.y + bmbase, bn = blockIdx.x;
    const __half* Ab = g_Ah + (size_t)bm * 128 * 2048;
    const __half* Wb = g_Wh + (size_t)bn * 128 * 2048;
    unsigned s0 = (unsigned)__cvta_generic_to_shared(smem);

    float c[4][8][4];
#pragma unroll
    for (int i = 0; i < 4; i++)
#pragma unroll
        for (int j = 0; j < 8; j++)
#pragma unroll
            for (int r = 0; r < 4; r++) c[i][j][r] = 0.f;

    fill2(Ab, Wb, s0, 0, tid);
    asm volatile("cp.async.commit_group;\n");
    fill2(Ab, Wb, s0 + 32768, 1, tid);
    asm volatile("cp.async.commit_group;\n");

#pragma unroll 1
    for (int f = 0; f < 32; f++) {
        asm volatile("cp.async.wait_group 1;\n" ::: "memory");  // stage f landed
        __syncthreads();
        const char* a_sb = smem + (f & 1) * 32768;
        const char* w_sb = a_sb + 16384;
#pragma unroll
        for (int kt4 = 0; kt4 < 4; kt4++) {
            uint4 af[4];
#pragma unroll
            for (int i = 0; i < 4; i++) {
                int mi = wm * 4 + i;
                af[i] = *reinterpret_cast<const uint4*>(a_sb + kt4 * 4096 + mi * 512 + lane * 16);
            }
#pragma unroll
            for (int jp = 0; jp < 4; jp++) {
                int ni = wn * 8 + jp * 2;
                uint2 b0 = *reinterpret_cast<const uint2*>(w_sb + kt4 * 4096 + ni * 256 + lane * 8);
                uint2 b1 = *reinterpret_cast<const uint2*>(w_sb + kt4 * 4096 + (ni + 1) * 256 + lane * 8);
#pragma unroll
                for (int i = 0; i < 4; i++) {
                    asm volatile(
                        "mma.sync.aligned.m16n8k16.row.col.f32.f16.f16.f32 "
                        "{%0,%1,%2,%3},{%4,%5,%6,%7},{%8,%9},{%0,%1,%2,%3};\n"
                        : "+f"(c[i][jp*2][0]), "+f"(c[i][jp*2][1]), "+f"(c[i][jp*2][2]), "+f"(c[i][jp*2][3])
                        : "r"(af[i].x), "r"(af[i].y), "r"(af[i].z), "r"(af[i].w),
                          "r"(b0.x), "r"(b0.y));
                    asm volatile(
                        "mma.sync.aligned.m16n8k16.row.col.f32.f16.f16.f32 "
                        "{%0,%1,%2,%3},{%4,%5,%6,%7},{%8,%9},{%0,%1,%2,%3};\n"
                        : "+f"(c[i][jp*2+1][0]), "+f"(c[i][jp*2+1][1]), "+f"(c[i][jp*2+1][2]), "+f"(c[i][jp*2+1][3])
                        : "r"(af[i].x), "r"(af[i].y), "r"(af[i].z), "r"(af[i].w),
                          "r"(b1.x), "r"(b1.y));
                }
            }
        }
        __syncthreads();                              // all readers of buf f&1 done
        if (f + 2 < 32) fill2(Ab, Wb, s0 + (f & 1) * 32768, f + 2, tid);
        asm volatile("cp.async.commit_group;\n");
    }

    // epilogue: bias + relu + fp32 store + fused column sum/sumsq
    float* sWsum = (float*)smem;          // [2][128] indexed by wm
    float* sWsq  = (float*)smem + 256;
    int g = lane >> 2, c2 = (lane & 3) * 2;
#pragma unroll
    for (int j = 0; j < 8; j++) {
        int col = bn * 128 + wn * 64 + j * 8 + c2;
        float b0 = bias[col], b1 = bias[col + 1];
        float sA = 0.f, sB = 0.f, qA = 0.f, qB = 0.f;
#pragma unroll
        for (int i = 0; i < 4; i++) {
            int row0 = bm * 128 + wm * 64 + i * 16 + g;
            float2 v0 = make_float2(fmaxf(c[i][j][0] + b0, 0.f), fmaxf(c[i][j][1] + b1, 0.f));
            float2 v1 = make_float2(fmaxf(c[i][j][2] + b0, 0.f), fmaxf(c[i][j][3] + b1, 0.f));
            *reinterpret_cast<float2*>(&g_out[(size_t)row0 * 2048 + col]) = v0;
            *reinterpret_cast<float2*>(&g_out[(size_t)(row0 + 8) * 2048 + col]) = v1;
            sA += v0.x + v1.x; qA += v0.x * v0.x + v1.x * v1.x;
            sB += v0.y + v1.y; qB += v0.y * v0.y + v1.y * v1.y;
        }
#pragma unroll
        for (int m = 4; m <= 16; m <<= 1) {
            sA += __shfl_xor_sync(0xFFFFFFFFu, sA, m);
            sB += __shfl_xor_sync(0xFFFFFFFFu, sB, m);
            qA += __shfl_xor_sync(0xFFFFFFFFu, qA, m);
            qB += __shfl_xor_sync(0xFFFFFFFFu, qB, m);
        }
        if (lane < 4) {
            int cl = wn * 64 + j * 8 + lane * 2;
            sWsum[wm * 128 + cl]     = sA;
            sWsum[wm * 128 + cl + 1] = sB;
            sWsq[wm * 128 + cl]      = qA;
            sWsq[wm * 128 + cl + 1]  = qB;
        }
    }
    __syncthreads();
    size_t po = (size_t)bm * 2048 + bn * 128 + tid;
    g_psum[po]   = sWsum[tid] + sWsum[128 + tid];
    g_psumsq[po] = sWsq[tid]  + sWsq[128 + tid];
}

// ---------------- kernel 4: finalize mean/var (parallel) -------------------
__global__ void k_final(const float* __restrict__ gamma, const float* __restrict__ beta) {
    int col = blockIdx.x * 32 + (threadIdx.x >> 3);   // 64 blocks x 32 cols
    int part = threadIdx.x & 7;
    float s = 0.f, ss = 0.f;
#pragma unroll
    for (int ch = part; ch < 128; ch += 8) {
        s  += g_psum[(size_t)ch * 2048 + col];
        ss += g_psumsq[(size_t)ch * 2048 + col];
    }
#pragma unroll
    for (int off = 4; off > 0; off >>= 1) {
        s  += __shfl_down_sync(0xFFFFFFFFu, s, off, 8);
        ss += __shfl_down_sync(0xFFFFFFFFu, ss, off, 8);
    }
    if (part == 0) {
        float mean = s * (1.0f / 16384.0f);
        float var = ss * (1.0f / 16384.0f) - mean * mean;
        float inv = rsqrtf(var + 1e-5f);
        float sc = inv * gamma[col];
        g_scale[col] = sc;
        g_shift[col] = beta[col] - mean * sc;
    }
}

// ---------------- kernel 5: apply BN affine --------------------------------
__global__ void k_apply(float* __restrict__ y) {
    size_t idx = (size_t)blockIdx.x * blockDim.x + threadIdx.x;
    float4 v = reinterpret_cast<const float4*>(g_out)[idx];
    int col = ((int)idx * 4) & 2047;
    float4 r;
    r.x = v.x * g_scale[col]     + g_shift[col];
    r.y = v.y * g_scale[col + 1] + g_shift[col + 1];
    r.z = v.z * g_scale[col + 2] + g_shift[col + 2];
    r.w = v.w * g_scale[col + 3] + g_shift[col + 3];
    reinterpret_cast<float4*>(y)[idx] = r;
}

// ---------------- launch: proven R13 fork-join (capture-legal) --------------
extern "C" void kernel_launch(void* const* d_in, const int* in_sizes, int n_in,
                              void* d_out, int out_size) {
    (void)in_sizes; (void)n_in; (void)out_size;
    const float* x      = (const float*)d_in[0];
    const float* W      = (const float*)d_in[1];
    const float* bias   = (const float*)d_in[2];
    const float* center = (const float*)d_in[3];
    const float* sharp  = (const float*)d_in[4];
    const float* gamma  = (const float*)d_in[5];
    const float* beta   = (const float*)d_in[6];
    float* y      = (float*)d_out;                       // [B, DOUT]
    float* mu_out = (float*)d_out + (size_t)BSZ * DOUT;  // [B, DIN]

    cudaFuncSetAttribute(k_gemm, cudaFuncAttributeMaxDynamicSharedMemorySize, GEMM_SMEM);

    // s0: wconv -> mu half0
    k_wconv<<<1024, 256>>>(W);
    k_mu_topk<<<BSZ / 2, 256>>>(x, center, sharp, mu_out, 0);
    cudaEventRecord(g_evM0, 0);

    // s1 (forked after mu0 — first op on s1 is the event wait, capture-legal):
    // mu half1 runs concurrently with gemm half0 on s0
    cudaStreamWaitEvent(g_s1, g_evM0, 0);
    k_mu_topk<<<BSZ / 2, 256, 0, g_s1>>>(x, center, sharp, mu_out, BSZ / 2);
    k_gemm<<<dim3(DOUT / 128, 64), 128, GEMM_SMEM>>>(bias, 0);          // bm 0..63
    k_gemm<<<dim3(DOUT / 128, 64), 128, GEMM_SMEM, g_s1>>>(bias, 64);   // bm 64..127
    cudaEventRecord(g_evJ, g_s1);

    // join: BN finalize + apply need both gemm halves
    cudaStreamWaitEvent(0, g_evJ, 0);
    k_final<<<64, 256>>>(gamma, beta);
    k_apply<<<32768, 256>>>(y);
}